// round 5
// baseline (speedup 1.0000x reference)
#include <cuda_runtime.h>

typedef unsigned long long u64;

#define NT 448
#define BT 56
#define RSTR 58          /* float stride for natural buffers */
#define HD 58            /* u64 stride for dup h buffer (even -> 16B aligned) */
#define B_TOT 8192
#define T_STEPS 30
#define WARM 24

__device__ __forceinline__ u64 pack2(float lo, float hi){
    u64 r; asm("mov.b64 %0, {%1, %2};" : "=l"(r) : "f"(lo), "f"(hi)); return r;
}
__device__ __forceinline__ void unpack2(u64 v, float& lo, float& hi){
    asm("mov.b64 {%0, %1}, %2;" : "=f"(lo), "=f"(hi) : "l"(v));
}
__device__ __forceinline__ u64 fma2(u64 a, u64 b, u64 c){
    u64 d; asm("fma.rn.f32x2 %0, %1, %2, %3;" : "=l"(d) : "l"(a), "l"(b), "l"(c)); return d;
}
__device__ __forceinline__ float sig_(float x){ return __fdividef(1.f, 1.f + __expf(-x)); }
__device__ __forceinline__ float tanh_(float x){ return 1.f - 2.f * __fdividef(1.f, __expf(2.f * x) + 1.f); }

// smem: hdup[136][HD] u64, then floats: hnat 128*58, m1 128*58, wsm 2*4096, red 112, predb 56
#define SMEM_BYTES (136*HD*8 + (128*RSTR + 128*RSTR + 8192 + 2*BT + BT) * 4)

__global__ void __launch_bounds__(NT, 1)
fused_lstm_kernel(const float* __restrict__ x0, const float* __restrict__ x1,
                  const float* __restrict__ x2, const float* __restrict__ x3,
                  const float* __restrict__ x4, const float* __restrict__ x5,
                  const float* __restrict__ x6, const float* __restrict__ irr,
                  const float* __restrict__ Wi, const float* __restrict__ Wh,
                  const float* __restrict__ bz, const float* __restrict__ W1,
                  const float* __restrict__ b1, const float* __restrict__ W2,
                  const float* __restrict__ b2, const float* __restrict__ Wout,
                  const float* __restrict__ bout, float* __restrict__ out)
{
    extern __shared__ u64 sm[];
    u64*   hdupU = sm;                        // [136][HD]: k 0-127 h dup, 128-135 inputs dup
    float* hnat  = (float*)(sm + 136 * HD);   // [128][58] natural h (for MLP-1)
    float* m1b   = hnat + 128 * RSTR;         // [128][58]
    float* wsm   = m1b  + 128 * RSTR;         // 2 x 4096 weight staging
    float* red   = wsm  + 8192;               // [2][56]
    float* predb = red  + 2 * BT;             // [56]

    const int tid = threadIdx.x;
    const int rg  = tid >> 6;                 // 0..6 : 8 batch rows each
    const int cg  = tid & 63;                 // 0..63: 2 channels each
    const int r0  = rg << 3;
    const int ch0 = cg << 1;
    const int b0  = blockIdx.x * BT;

    // ---- constants to registers (natural channel pairs) ----
    u64 bzr[4];
    #pragma unroll
    for (int q = 0; q < 4; q++) bzr[q] = *reinterpret_cast<const u64*>(&bz[(q << 7) + ch0]);
    const u64 cb1r = *reinterpret_cast<const u64*>(&b1[ch0]);
    const u64 cb2r = *reinterpret_cast<const u64*>(&b2[ch0]);
    const float wo0 = Wout[ch0], wo1 = Wout[ch0 + 1];
    const float boutv = bout[0];

    // ---- input feature pointers: 8 feats x 56 rows ----
    const int lf = tid / BT, lr = tid - lf * BT;
    int lb = b0 + lr; if (lb > B_TOT - 1) lb = B_TOT - 1;
    const float* fptr;
    if      (lf == 0) fptr = x0; else if (lf == 1) fptr = x1;
    else if (lf == 2) fptr = x2; else if (lf == 3) fptr = x3;
    else if (lf == 4) fptr = x4; else if (lf == 5) fptr = x5;
    else if (lf == 6) fptr = x6; else              fptr = irr;
    fptr = (lf < 7) ? (fptr + lb * T_STEPS) : (fptr + lb * WARM);
    const int tmax = (lf < 7) ? (T_STEPS - 1) : (WARM - 1);
    float vin = __ldg(fptr);

    // ---- init h = 0 (dup + natural) ----
    for (int i = tid; i < 128 * HD; i += NT) hdupU[i] = 0ull;
    for (int i = tid; i < 128 * RSTR; i += NT) hnat[i] = 0.f;

    // ---- prologue: stage Wh chunk 0 ----
    {
        const float4* s4 = reinterpret_cast<const float4*>(Wh);
        float4* d4 = reinterpret_cast<float4*>(wsm);
        d4[tid] = s4[tid];
        d4[tid + 448] = s4[tid + 448];
        if (tid < 128) d4[tid + 896] = s4[tid + 896];
    }
    int pb = 0;

    // c-state: 8 rows, channel pair packed
    u64 cst[8];
    #pragma unroll
    for (int j = 0; j < 8; j++) cst[j] = 0ull;

    __syncthreads();

    for (int t = 0; t < T_STEPS; ++t){
        // ---- stage input (dup) rows 128..135; prefetch next step's ----
        {
            float v = (lf < 7 || t < WARM) ? vin : predb[lr];
            hdupU[(128 + lf) * HD + lr] = pack2(v, v);
            int tn = (t + 1 < tmax) ? (t + 1) : tmax;
            vin = __ldg(fptr + tn);
        }

        // ================= z = [h, inp] @ [Wh; Wi] + b =================
        // acc[j][q] = (z_{q*128+ch0}, z_{q*128+ch0+1}) for row r0+j
        u64 acc[8][4];
        #pragma unroll
        for (int j = 0; j < 8; j++){
            acc[j][0] = bzr[0]; acc[j][1] = bzr[1];
            acc[j][2] = bzr[2]; acc[j][3] = bzr[3];
        }

        for (int c = 0; c <= 16; ++c){
            const float* src = (c < 15) ? (Wh + (c + 1) * 4096) : ((c == 15) ? Wi : W1);
            const float4* s4 = reinterpret_cast<const float4*>(src);
            float4 v0 = s4[tid];
            float4 v1 = s4[tid + 448];
            float4 v2; if (tid < 128) v2 = s4[tid + 896];

            const float* wb = wsm + (pb << 12);
            const int k0 = c << 3;
            #pragma unroll
            for (int kk = 0; kk < 8; kk++){
                const u64* hd = hdupU + (k0 + kk) * HD + r0;
                ulonglong2 A = *reinterpret_cast<const ulonglong2*>(hd);
                ulonglong2 Bv = *reinterpret_cast<const ulonglong2*>(hd + 2);
                ulonglong2 C = *reinterpret_cast<const ulonglong2*>(hd + 4);
                ulonglong2 D = *reinterpret_cast<const ulonglong2*>(hd + 6);
                #pragma unroll
                for (int q = 0; q < 4; q++){
                    u64 wp = *reinterpret_cast<const u64*>(&wb[(kk << 9) + (q << 7) + ch0]);
                    acc[0][q] = fma2(A.x,  wp, acc[0][q]);
                    acc[1][q] = fma2(A.y,  wp, acc[1][q]);
                    acc[2][q] = fma2(Bv.x, wp, acc[2][q]);
                    acc[3][q] = fma2(Bv.y, wp, acc[3][q]);
                    acc[4][q] = fma2(C.x,  wp, acc[4][q]);
                    acc[5][q] = fma2(C.y,  wp, acc[5][q]);
                    acc[6][q] = fma2(D.x,  wp, acc[6][q]);
                    acc[7][q] = fma2(D.y,  wp, acc[7][q]);
                }
            }
            float4* d4 = reinterpret_cast<float4*>(wsm + ((pb ^ 1) << 12));
            d4[tid] = v0;
            d4[tid + 448] = v1;
            if (tid < 128) d4[tid + 896] = v2;
            __syncthreads();
            pb ^= 1;
        }

        // ================= gates; write h dup + natural =================
        #pragma unroll
        for (int j = 0; j < 8; j++){
            float i0,i1,f0,f1,g0,g1,o0,o1,c0,c1;
            unpack2(acc[j][0], i0, i1);
            unpack2(acc[j][1], f0, f1);
            unpack2(acc[j][2], g0, g1);
            unpack2(acc[j][3], o0, o1);
            unpack2(cst[j], c0, c1);
            c0 = sig_(f0)*c0 + sig_(i0)*tanh_(g0);
            c1 = sig_(f1)*c1 + sig_(i1)*tanh_(g1);
            cst[j] = pack2(c0, c1);
            float h0 = sig_(o0)*tanh_(c0);
            float h1 = sig_(o1)*tanh_(c1);
            int row = r0 + j;
            hnat[ ch0      * RSTR + row] = h0;
            hnat[(ch0 + 1) * RSTR + row] = h1;
            hdupU[ ch0      * HD + row] = pack2(h0, h0);
            hdupU[(ch0 + 1) * HD + row] = pack2(h1, h1);
        }
        __syncthreads();

        // ================= m1 = relu(h @ W1 + b1)  (row-pair packed) =================
        u64 a1[4][2];
        {
            float q0, q1; unpack2(cb1r, q0, q1);
            u64 p0 = pack2(q0,q0), p1 = pack2(q1,q1);
            #pragma unroll
            for (int rp = 0; rp < 4; rp++){ a1[rp][0] = p0; a1[rp][1] = p1; }
        }
        for (int c = 0; c < 4; ++c){
            const float* src = (c < 3) ? (W1 + (c + 1) * 4096) : W2;
            const float4* s4 = reinterpret_cast<const float4*>(src);
            float4 v0 = s4[tid];
            float4 v1 = s4[tid + 448];
            float4 v2; if (tid < 128) v2 = s4[tid + 896];

            const float* wb = wsm + (pb << 12);
            const int k0 = c << 5;
            #pragma unroll 8
            for (int kk = 0; kk < 32; kk++){
                const u64* h64 = reinterpret_cast<const u64*>(hnat + (k0 + kk) * RSTR + r0);
                u64 hp0 = h64[0], hp1 = h64[1], hp2 = h64[2], hp3 = h64[3];
                u64 wp = *reinterpret_cast<const u64*>(&wb[(kk << 7) + ch0]);
                float w0, w1; unpack2(wp, w0, w1);
                u64 w00 = pack2(w0, w0), w11 = pack2(w1, w1);
                a1[0][0] = fma2(hp0, w00, a1[0][0]);
                a1[1][0] = fma2(hp1, w00, a1[1][0]);
                a1[2][0] = fma2(hp2, w00, a1[2][0]);
                a1[3][0] = fma2(hp3, w00, a1[3][0]);
                a1[0][1] = fma2(hp0, w11, a1[0][1]);
                a1[1][1] = fma2(hp1, w11, a1[1][1]);
                a1[2][1] = fma2(hp2, w11, a1[2][1]);
                a1[3][1] = fma2(hp3, w11, a1[3][1]);
            }
            float4* d4 = reinterpret_cast<float4*>(wsm + ((pb ^ 1) << 12));
            d4[tid] = v0;
            d4[tid + 448] = v1;
            if (tid < 128) d4[tid + 896] = v2;
            __syncthreads();
            pb ^= 1;
        }
        #pragma unroll
        for (int rp = 0; rp < 4; rp++)
            #pragma unroll
            for (int d = 0; d < 2; d++){
                float v0, v1; unpack2(a1[rp][d], v0, v1);
                *reinterpret_cast<u64*>(&m1b[(ch0+d)*RSTR + r0 + (rp<<1)]) =
                    pack2(fmaxf(v0, 0.f), fmaxf(v1, 0.f));
            }
        __syncthreads();

        // ================= m2 = relu(m1 @ W2 + b2) =================
        u64 a2[4][2];
        {
            float q0, q1; unpack2(cb2r, q0, q1);
            u64 p0 = pack2(q0,q0), p1 = pack2(q1,q1);
            #pragma unroll
            for (int rp = 0; rp < 4; rp++){ a2[rp][0] = p0; a2[rp][1] = p1; }
        }
        for (int c = 0; c < 4; ++c){
            const float* src = (c < 3) ? (W2 + (c + 1) * 4096) : Wh;  // last: next step's chunk 0
            const float4* s4 = reinterpret_cast<const float4*>(src);
            float4 v0 = s4[tid];
            float4 v1 = s4[tid + 448];
            float4 v2; if (tid < 128) v2 = s4[tid + 896];

            const float* wb = wsm + (pb << 12);
            const int k0 = c << 5;
            #pragma unroll 8
            for (int kk = 0; kk < 32; kk++){
                const u64* h64 = reinterpret_cast<const u64*>(m1b + (k0 + kk) * RSTR + r0);
                u64 hp0 = h64[0], hp1 = h64[1], hp2 = h64[2], hp3 = h64[3];
                u64 wp = *reinterpret_cast<const u64*>(&wb[(kk << 7) + ch0]);
                float w0, w1; unpack2(wp, w0, w1);
                u64 w00 = pack2(w0, w0), w11 = pack2(w1, w1);
                a2[0][0] = fma2(hp0, w00, a2[0][0]);
                a2[1][0] = fma2(hp1, w00, a2[1][0]);
                a2[2][0] = fma2(hp2, w00, a2[2][0]);
                a2[3][0] = fma2(hp3, w00, a2[3][0]);
                a2[0][1] = fma2(hp0, w11, a2[0][1]);
                a2[1][1] = fma2(hp1, w11, a2[1][1]);
                a2[2][1] = fma2(hp2, w11, a2[2][1]);
                a2[3][1] = fma2(hp3, w11, a2[3][1]);
            }
            float4* d4 = reinterpret_cast<float4*>(wsm + ((pb ^ 1) << 12));
            d4[tid] = v0;
            d4[tid + 448] = v1;
            if (tid < 128) d4[tid + 896] = v2;
            __syncthreads();
            pb ^= 1;
        }

        // ---- out-projection in registers + warp shuffle reduce ----
        float p[8];
        #pragma unroll
        for (int rp = 0; rp < 4; rp++){
            float v0a, v0b, v1a, v1b;
            unpack2(a2[rp][0], v0a, v0b);
            unpack2(a2[rp][1], v1a, v1b);
            p[(rp<<1)  ] = fmaxf(v0a, 0.f) * wo0 + fmaxf(v1a, 0.f) * wo1;
            p[(rp<<1)+1] = fmaxf(v0b, 0.f) * wo0 + fmaxf(v1b, 0.f) * wo1;
        }
        #pragma unroll
        for (int j = 0; j < 8; j++)
            #pragma unroll
            for (int off = 16; off; off >>= 1)
                p[j] += __shfl_xor_sync(0xffffffffu, p[j], off);
        if ((tid & 31) == 0){
            int half = (tid >> 5) & 1;
            #pragma unroll
            for (int j = 0; j < 8; j++) red[half * BT + r0 + j] = p[j];
        }
        __syncthreads();
        if (tid < BT){
            float s = boutv + red[tid] + red[BT + tid];
            predb[tid] = s;
            int bb = b0 + tid;
            if (bb < B_TOT) out[bb * T_STEPS + t] = s;
        }
        __syncthreads();
    }
}

extern "C" void kernel_launch(void* const* d_in, const int* in_sizes, int n_in,
                              void* d_out, int out_size)
{
    (void)in_sizes; (void)n_in; (void)out_size;
    cudaFuncSetAttribute(fused_lstm_kernel, cudaFuncAttributeMaxDynamicSharedMemorySize, SMEM_BYTES);
    int grid = (B_TOT + BT - 1) / BT; // 147
    fused_lstm_kernel<<<grid, NT, SMEM_BYTES>>>(
        (const float*)d_in[8],  (const float*)d_in[9],  (const float*)d_in[10],
        (const float*)d_in[11], (const float*)d_in[12], (const float*)d_in[13],
        (const float*)d_in[14], (const float*)d_in[15],
        (const float*)d_in[16], (const float*)d_in[17], (const float*)d_in[18],
        (const float*)d_in[19], (const float*)d_in[20], (const float*)d_in[21],
        (const float*)d_in[22], (const float*)d_in[23], (const float*)d_in[24],
        (float*)d_out);
}